// round 15
// baseline (speedup 1.0000x reference)
#include <cuda_runtime.h>
#include <cuda_bf16.h>
#include <math.h>
#include <stdint.h>

#define N_TOK 4096
#define CIN 80
#define CMID 40

// ---------------- scratch (device globals; no allocs allowed) ----------------
__device__ float    g_xs[CIN * N_TOK];       // downsampled slow
__device__ uint32_t g_qhi[N_TOK * 44];       // theta tf32, padded [n][44]
__device__ uint32_t g_khi[N_TOK * 48];       // phi tf32, fragment-permuted rows
__device__ uint32_t g_vp[64 * 1664];         // V bf16 pairs, fragment-permuted per tile
__device__ float    g_wy[CIN * N_TOK];       // [c][n]
__device__ float    g_sum[CIN];
__device__ float    g_sumsq[CIN];

// ---------------- helpers ------------------------------------------------------
__device__ __forceinline__ uint32_t f2tf(float x) {
    uint32_t r; asm("cvt.rna.tf32.f32 %0, %1;" : "=r"(r) : "f"(x)); return r;
}
__device__ __forceinline__ uint32_t packbf(float lo, float hi) {
    uint32_t r; asm("cvt.rn.bf16x2.f32 %0, %1, %2;" : "=r"(r) : "f"(hi), "f"(lo)); return r;
}

__device__ __forceinline__ void mma8(float c[4], uint32_t a0, uint32_t a1, uint32_t a2, uint32_t a3,
                                     uint32_t b0, uint32_t b1) {
    asm volatile("mma.sync.aligned.m16n8k8.row.col.f32.tf32.tf32.f32 "
                 "{%0,%1,%2,%3}, {%4,%5,%6,%7}, {%8,%9}, {%0,%1,%2,%3};"
                 : "+f"(c[0]), "+f"(c[1]), "+f"(c[2]), "+f"(c[3])
                 : "r"(a0), "r"(a1), "r"(a2), "r"(a3), "r"(b0), "r"(b1));
}
__device__ __forceinline__ void mma16(float c[4], uint32_t a0, uint32_t a1, uint32_t a2, uint32_t a3,
                                      uint32_t b0, uint32_t b1) {
    asm volatile("mma.sync.aligned.m16n8k16.row.col.f32.bf16.bf16.f32 "
                 "{%0,%1,%2,%3}, {%4,%5,%6,%7}, {%8,%9}, {%0,%1,%2,%3};"
                 : "+f"(c[0]), "+f"(c[1]), "+f"(c[2]), "+f"(c[3])
                 : "r"(a0), "r"(a1), "r"(a2), "r"(a3), "r"(b0), "r"(b1));
}

__device__ __forceinline__ void cpa16(uint32_t dst, const void* src) {
    asm volatile("cp.async.cg.shared.global [%0], [%1], 16;" :: "r"(dst), "l"(src));
}
__device__ __forceinline__ void cpa_commit() { asm volatile("cp.async.commit_group;"); }
__device__ __forceinline__ void cpa_wait0()  { asm volatile("cp.async.wait_group 0;"); }

__device__ __forceinline__ uint32_t smem_u32(const void* p) {
    uint32_t r;
    asm("{ .reg .u64 t; cvta.to.shared.u64 t, %1; cvt.u32.u64 %0, t; }" : "=r"(r) : "l"(p));
    return r;
}

__device__ __forceinline__ void wg_bar(int wg) {
    asm volatile("bar.sync %0, 256;" :: "r"(wg + 1) : "memory");
}

// ---------------- 0) profiling-slot shim (no-op node) -------------------------
__global__ void k_nop() {}

// ---------------- downsample weights (jax linear, antialias=True) -------------
__device__ __forceinline__ void down_w(int o, int& r0, float w[4]) {
    if (o == 0)        { r0 = -1; w[0] = 0.f;       w[1] = 3.f/7.f; w[2] = 3.f/7.f; w[3] = 1.f/7.f; }
    else if (o == 31)  { r0 = 61; w[0] = 1.f/7.f;   w[1] = 3.f/7.f; w[2] = 3.f/7.f; w[3] = 0.f; }
    else               { r0 = 2*o - 1; w[0] = 0.125f; w[1] = 0.375f; w[2] = 0.375f; w[3] = 0.125f; }
}

// ---------------- 1) FUSED prep: [0..127] proj(fast) | [128..447] down(slow) --
__global__ void __launch_bounds__(256) k_prep(const float* __restrict__ fast,
                       const float* __restrict__ slow,
                       const float* __restrict__ gw, const float* __restrict__ gb,
                       const float* __restrict__ thw, const float* __restrict__ thb,
                       const float* __restrict__ phw, const float* __restrict__ phb) {
    __shared__ float smbuf[12288];   // 48KB union
    int p = blockIdx.x;
    int tid = threadIdx.x;

    if (p >= 128) {
        // ---- slow-path downsample: plane q = p-128 (c*4+t) ----
        int q = p - 128;
        if (q == 0) {
            if (tid < 80)       g_sum[tid] = 0.f;
            else if (tid < 160) g_sumsq[tid - 80] = 0.f;
        }
        float* s = smbuf;            // 4096 floats
        const float* plane = slow + (size_t)q * 4096;
        for (int i = tid; i < 4096; i += 256) s[i] = plane[i];
        __syncthreads();
        for (int i = tid; i < 1024; i += 256) {
            int ho = i >> 5, wo = i & 31;
            int rh, rw; float wh[4], ww[4];
            down_w(ho, rh, wh);
            down_w(wo, rw, ww);
            float acc = 0.f;
#pragma unroll
            for (int a = 0; a < 4; a++) {
                int r = min(max(rh + a, 0), 63);
                float rowacc = 0.f;
#pragma unroll
                for (int b = 0; b < 4; b++) {
                    int cc = min(max(rw + b, 0), 63);
                    rowacc += ww[b] * s[r * 64 + cc];
                }
                acc += wh[a] * rowacc;
            }
            g_xs[q * 1024 + i] = acc;
        }
        return;
    }

    // ---- fast-path: downsample + projection for (t,h) slab of 32 tokens ----
    float* Ws = smbuf;               // 9600
    float* Bs = smbuf + 9600;        // 120 (pad to 128)
    float* Xs = smbuf + 9728;        // 2560
    int t = p >> 5, h = p & 31;

    for (int i = tid; i < 3200; i += 256) {
        Ws[i]        = thw[i];
        Ws[3200 + i] = phw[i];
        Ws[6400 + i] = gw[i];
    }
    if (tid < 120) {
        int o = tid;
        Bs[o] = (o < 40) ? thb[o] : (o < 80 ? phb[o - 40] : gb[o - 80]);
    }

    int rh; float wh[4];
    down_w(h, rh, wh);
    int rr[4];
#pragma unroll
    for (int a = 0; a < 4; a++) rr[a] = min(max(rh + a, 0), 63);
#pragma unroll
    for (int k = 0; k < 10; k++) {
        int i = tid + 256 * k;
        int c = i >> 5, wo = i & 31;
        int rw; float ww[4];
        down_w(wo, rw, ww);
        int cc[4];
#pragma unroll
        for (int b = 0; b < 4; b++) cc[b] = min(max(rw + b, 0), 63);
        const float* base = fast + ((size_t)(c * 4 + t)) * 4096;
        float acc = 0.f;
#pragma unroll
        for (int a = 0; a < 4; a++) {
            const float* row = base + rr[a] * 64;
            float rowacc = ww[0] * __ldg(row + cc[0]) + ww[1] * __ldg(row + cc[1])
                         + ww[2] * __ldg(row + cc[2]) + ww[3] * __ldg(row + cc[3]);
            acc += wh[a] * rowacc;
        }
        Xs[c * 32 + wo] = acc;
    }
    __syncthreads();

    int n  = tid & 31;
    int og = tid >> 5;
    float acc[15];
#pragma unroll
    for (int j = 0; j < 15; j++) acc[j] = Bs[og + 8 * j];
    for (int c = 0; c < 80; c++) {
        float xv = Xs[c * 32 + n];
#pragma unroll
        for (int j = 0; j < 15; j++) acc[j] += Ws[(og + 8 * j) * 80 + c] * xv;
    }
    int nn = p * 32 + n;
    int tile = nn >> 6, key = nn & 63;
#pragma unroll
    for (int j = 0; j < 15; j++) {
        int o = og + 8 * j;
        float v = acc[j];
        if (o < 40) {
            g_qhi[nn * 44 + o] = f2tf(v);
        } else if (o < 80) {
            int k = o - 40;
            g_khi[nn * 48 + (k & 3) * 12 + (k >> 2)] = f2tf(v);
        } else {
            int d = o - 80;
            int pair = key >> 1, b = key & 1;
            int wc = pair >> 3, m = pair & 7;
            int tg = m & 3, mp = m >> 2;
            int off = wc * 416 + tg * 104 + (d & 7) * 12 + (d >> 3) * 2 + mp;
            ((__nv_bfloat16*)g_vp)[((size_t)tile * 1664 + off) * 2 + b] = __float2bfloat16(v);
        }
    }
}

// ---------------- 2) attention + wz projection + BN stats (fused) -----------
#define SM_QH   0
#define WG_BASE 1408
#define WG_STRIDE 18944
#define WG_VOFF 12288
#define SM_SML  39296
#define SM_O1   39552
#define SM_L1   40832
#define SM_YS   40864
#define SM_WZS  42144
#define SM_TOT  45344

__device__ __forceinline__ void stage_kv(uint32_t sb, int tile, int wg, int buf, int wtid) {
    const char* sk = (const char*)(g_khi + tile * 3072);
    uint32_t dk = sb + (WG_BASE + wg * WG_STRIDE + buf * 3072) * 4;
#pragma unroll
    for (int i = wtid * 16; i < 768 * 16; i += 256 * 16)
        cpa16(dk + i, sk + i);
    const char* sv = (const char*)(g_vp + (size_t)tile * 1664);
    uint32_t dv = sb + (WG_BASE + wg * WG_STRIDE + WG_VOFF + buf * 1664) * 4;
#pragma unroll
    for (int i = wtid * 16; i < 416 * 16; i += 256 * 16)
        cpa16(dv + i, sv + i);
}

__global__ void __launch_bounds__(512, 1) k_attn_tc(const float* __restrict__ wzw,
                                                    const float* __restrict__ wzb) {
    extern __shared__ uint32_t sm[];
    uint32_t sb = smem_u32(sm);

    int tid  = threadIdx.x;
    int lane = tid & 31, wid = tid >> 5;
    int g = lane >> 2, tig = lane & 3;
    int wg = tid >> 8;
    int wtid = tid & 255;
    int wlocal = wid & 7;
    int warp_m = wlocal & 1, warp_c = wlocal >> 1;
    int m0 = blockIdx.x * 32;
    int rb = warp_m * 16;
    int r0 = rb + g, r1 = rb + g + 8;
    int wgt0 = wg * 32;

    {
        const char* sqh = (const char*)(g_qhi + m0 * 44);
#pragma unroll
        for (int i = tid * 16; i < 352 * 16; i += 512 * 16)
            cpa16(sb + i, sqh + i);
        stage_kv(sb, wgt0,     wg, 0, wtid);
        stage_kv(sb, wgt0 + 1, wg, 1, wtid);
        cpa_commit();
        cpa_wait0();
        __syncthreads();
    }

    uint32_t qh[5][4];
#pragma unroll
    for (int ks = 0; ks < 5; ks++) {
        int k0 = 8 * ks;
        qh[ks][0] = sm[SM_QH + r0 * 44 + k0 + tig];
        qh[ks][1] = sm[SM_QH + r1 * 44 + k0 + tig];
        qh[ks][2] = sm[SM_QH + r0 * 44 + k0 + tig + 4];
        qh[ks][3] = sm[SM_QH + r1 * 44 + k0 + tig + 4];
    }

    float oacc[5][4];
#pragma unroll
    for (int i = 0; i < 5; i++)
#pragma unroll
        for (int j = 0; j < 4; j++) oacc[i][j] = 0.f;
    float l0 = 0.f, l1 = 0.f;

    const uint32_t* wgk = sm + WG_BASE + wg * WG_STRIDE;
    const uint32_t* wgv = wgk + WG_VOFF;

    auto do_tile = [&](int buf) {
        const uint32_t* kh = wgk + buf * 3072;
        const uint32_t* vt = wgv + buf * 1664;

        uint32_t kv[2][10];
#pragma unroll
        for (int nt = 0; nt < 2; nt++) {
            const uint32_t* kp = kh + (16 * warp_c + 8 * nt + g) * 48 + tig * 12;
            uint4 a = *(const uint4*)kp;
            uint4 b = *(const uint4*)(kp + 4);
            uint2 c = *(const uint2*)(kp + 8);
            kv[nt][0] = a.x; kv[nt][1] = a.y; kv[nt][2] = a.z; kv[nt][3] = a.w;
            kv[nt][4] = b.x; kv[nt][5] = b.y; kv[nt][6] = b.z; kv[nt][7] = b.w;
            kv[nt][8] = c.x; kv[nt][9] = c.y;
        }

        float sA[2][4], sB[2][4];
#pragma unroll
        for (int i = 0; i < 2; i++)
#pragma unroll
            for (int j = 0; j < 4; j++) { sA[i][j] = 0.f; sB[i][j] = 0.f; }
#pragma unroll
        for (int nt = 0; nt < 2; nt++) {
            mma8(sA[nt], qh[0][0], qh[0][1], qh[0][2], qh[0][3], kv[nt][0], kv[nt][1]);
            mma8(sB[nt], qh[1][0], qh[1][1], qh[1][2], qh[1][3], kv[nt][2], kv[nt][3]);
            mma8(sA[nt], qh[2][0], qh[2][1], qh[2][2], qh[2][3], kv[nt][4], kv[nt][5]);
            mma8(sB[nt], qh[3][0], qh[3][1], qh[3][2], qh[3][3], kv[nt][6], kv[nt][7]);
            mma8(sA[nt], qh[4][0], qh[4][1], qh[4][2], qh[4][3], kv[nt][8], kv[nt][9]);
        }

        uint32_t vv[10];
        {
            const uint32_t* vpp = vt + warp_c * 416 + tig * 104 + g * 12;
            uint4 a = *(const uint4*)vpp;
            uint4 b = *(const uint4*)(vpp + 4);
            uint2 c = *(const uint2*)(vpp + 8);
            vv[0] = a.x; vv[1] = a.y; vv[2] = a.z; vv[3] = a.w;
            vv[4] = b.x; vv[5] = b.y; vv[6] = b.z; vv[7] = b.w;
            vv[8] = c.x; vv[9] = c.y;
        }

        float p[2][4];
#pragma unroll
        for (int nt = 0; nt < 2; nt++) {
#pragma unroll
            for (int j = 0; j < 4; j++) p[nt][j] = __expf(sA[nt][j] + sB[nt][j]);
            l0 += p[nt][0] + p[nt][1];
            l1 += p[nt][2] + p[nt][3];
        }

        uint32_t pa[4], pl[4];
#pragma unroll
        for (int nt = 0; nt < 2; nt++) {
            uint32_t h0 = packbf(p[nt][0], p[nt][1]);
            uint32_t h1 = packbf(p[nt][2], p[nt][3]);
            pa[2 * nt]     = h0;
            pa[2 * nt + 1] = h1;
            pl[2 * nt]     = packbf(p[nt][0] - __uint_as_float(h0 << 16),
                                    p[nt][1] - __uint_as_float(h0 & 0xffff0000u));
            pl[2 * nt + 1] = packbf(p[nt][2] - __uint_as_float(h1 << 16),
                                    p[nt][3] - __uint_as_float(h1 & 0xffff0000u));
        }

#pragma unroll
        for (int j = 0; j < 5; j++) {
            mma16(oacc[j], pa[0], pa[1], pa[2], pa[3], vv[2 * j], vv[2 * j + 1]);
            mma16(oacc[j], pl[0], pl[1], pl[2], pl[3], vv[2 * j], vv[2 * j + 1]);
        }
    };

    for (int it = 0; it < 16; it++) {
        int bp = (it & 1) << 1;
        if (it < 15) {
            int nbp = bp ^ 2;
            stage_kv(sb, wgt0 + 2 * it + 2, wg, nbp,     wtid);
            stage_kv(sb, wgt0 + 2 * it + 3, wg, nbp + 1, wtid);
            cpa_commit();
        }
        do_tile(bp);
        do_tile(bp + 1);
        if (it < 15) cpa_wait0();
        wg_bar(wg);
    }

    // ---- epilogue ----
    l0 += __shfl_xor_sync(0xffffffffu, l0, 1);
    l0 += __shfl_xor_sync(0xffffffffu, l0, 2);
    l1 += __shfl_xor_sync(0xffffffffu, l1, 1);
    l1 += __shfl_xor_sync(0xffffffffu, l1, 2);

    float* SMLw = (float*)(sm + SM_SML) + wg * 128;
    float* Obw  = (float*)(sm + WG_BASE + wg * WG_STRIDE);
    float* O1   = (float*)(sm + SM_O1);
    float* L1   = (float*)(sm + SM_L1);
    float* ys   = (float*)(sm + SM_YS);
    float4* wzs = (float4*)(sm + SM_WZS);

    if (tig == 0) { SMLw[warp_c * 32 + r0] = l0; SMLw[warp_c * 32 + r1] = l1; }
    if (warp_c > 0) {
        int base = (warp_c - 1) * 1280 + warp_m * 640;
#pragma unroll
        for (int j = 0; j < 5; j++) {
            int d = 8 * j + 2 * tig;
            *(float2*)&Obw[base + g * 40 + d]       = make_float2(oacc[j][0], oacc[j][1]);
            *(float2*)&Obw[base + (g + 8) * 40 + d] = make_float2(oacc[j][2], oacc[j][3]);
        }
    }
    for (int i = tid; i < 800; i += 512) wzs[i] = ((const float4*)wzw)[i];
    __syncthreads();

    if (warp_c == 0) {
        float L0s = 0.f, L1s = 0.f;
#pragma unroll
        for (int wc = 0; wc < 4; wc++) {
            L0s += SMLw[wc * 32 + r0];
            L1s += SMLw[wc * 32 + r1];
        }
        float o0[5][4];
#pragma unroll
        for (int j = 0; j < 5; j++) {
            int d = 8 * j + 2 * tig;
            o0[j][0] = oacc[j][0]; o0[j][1] = oacc[j][1];
            o0[j][2] = oacc[j][2]; o0[j][3] = oacc[j][3];
#pragma unroll
            for (int w = 0; w < 3; w++) {
                int base = w * 1280 + warp_m * 640;
                o0[j][0] += Obw[base + g * 40 + d];
                o0[j][1] += Obw[base + g * 40 + d + 1];
                o0[j][2] += Obw[base + (g + 8) * 40 + d];
                o0[j][3] += Obw[base + (g + 8) * 40 + d + 1];
            }
        }
        if (wg == 1) {
#pragma unroll
            for (int j = 0; j < 5; j++) {
                int d = 8 * j + 2 * tig;
                *(float2*)&O1[r0 * 40 + d] = make_float2(o0[j][0], o0[j][1]);
                *(float2*)&O1[r1 * 40 + d] = make_float2(o0[j][2], o0[j][3]);
            }
            if (tig == 0) { L1[r0] = L0s; L1[r1] = L1s; }
            __syncthreads();
        } else {
            __syncthreads();
            float il0 = 1.f / (L0s + L1[r0]);
            float il1 = 1.f / (L1s + L1[r1]);
#pragma unroll
            for (int j = 0; j < 5; j++) {
                int d = 8 * j + 2 * tig;
                float2 a = *(float2*)&O1[r0 * 40 + d];
                float2 b = *(float2*)&O1[r1 * 40 + d];
                *(float2*)&ys[r0 * 40 + d] = make_float2((o0[j][0] + a.x) * il0, (o0[j][1] + a.y) * il0);
                *(float2*)&ys[r1 * 40 + d] = make_float2((o0[j][2] + b.x) * il1, (o0[j][3] + b.y) * il1);
            }
        }
    } else {
        __syncthreads();
    }
    __syncthreads();

    {
        int n = lane;
        float4 yr[10];
#pragma unroll
        for (int q = 0; q < 10; q++) yr[q] = *(float4*)&ys[n * 40 + 4 * q];
#pragma unroll
        for (int j = 0; j < 5; j++) {
            int c = wid * 5 + j;
            float acc = wzb[c];
#pragma unroll
            for (int q = 0; q < 10; q++) {
                float4 w = wzs[c * 10 + q];
                acc += w.x * yr[q].x + w.y * yr[q].y + w.z * yr[q].z + w.w * yr[q].w;
            }
            g_wy[c * N_TOK + m0 + n] = acc;
            float s = acc, s2 = acc * acc;
#pragma unroll
            for (int off = 16; off > 0; off >>= 1) {
                s  += __shfl_down_sync(0xffffffffu, s, off);
                s2 += __shfl_down_sync(0xffffffffu, s2, off);
            }
            if (lane == 0) {
                atomicAdd(&g_sum[c], s);
                atomicAdd(&g_sumsq[c], s2);
            }
        }
    }
}

// ---------------- 3) normalize * slow, upsample 32->64 (half-plane CTAs) -----
__device__ __forceinline__ void up_w(int h, int& j0, float& w1) {
    if (h == 0)        { j0 = 0;  w1 = 0.f; }
    else if (h == 63)  { j0 = 31; w1 = 0.f; }
    else {
        float s = 0.5f * (float)h - 0.25f;
        j0 = (int)s;
        w1 = s - (float)j0;
    }
}

__global__ void __launch_bounds__(512) k_final(const float* __restrict__ bng,
                                               const float* __restrict__ bnb,
                                               float* __restrict__ out) {
    __shared__ float z[1024];
    int p = blockIdx.x >> 1;       // plane (c*4+t)
    int half = blockIdx.x & 1;     // output-row half
    int c = p >> 2;
    float mean = g_sum[c] * (1.f / 4096.f);
    float var  = g_sumsq[c] * (1.f / 4096.f) - mean * mean;
    float rstd = rsqrtf(var + 1e-5f);
    float ga = bng[c], be = bnb[c];
    for (int i = threadIdx.x; i < 1024; i += 512) {
        float wv = g_wy[c * N_TOK + (p & 3) * 1024 + i];
        float xs = g_xs[p * 1024 + i];
        z[i] = ((wv - mean) * rstd * ga + be) * xs;
    }
    __syncthreads();
    int wo = threadIdx.x & 63;     // invariant (512 % 64 == 0)
    int jw; float wwv;
    up_w(wo, jw, wwv);
    int jw1 = min(jw + 1, 31);
    for (int i = threadIdx.x; i < 2048; i += 512) {
        int ho = (i >> 6) + half * 32;
        int jh; float wh;
        up_w(ho, jh, wh);
        int jh1 = min(jh + 1, 31);
        float v00 = z[jh * 32 + jw],  v01 = z[jh * 32 + jw1];
        float v10 = z[jh1 * 32 + jw], v11 = z[jh1 * 32 + jw1];
        float v = (1.f - wh) * ((1.f - wwv) * v00 + wwv * v01)
                +        wh  * ((1.f - wwv) * v10 + wwv * v11);
        out[(size_t)p * 4096 + ho * 64 + wo] = v;
    }
}

// ---------------- launch ------------------------------------------------------
extern "C" void kernel_launch(void* const* d_in, const int* in_sizes, int n_in,
                              void* d_out, int out_size) {
    (void)in_sizes; (void)n_in; (void)out_size;
    const float* fast = (const float*)d_in[0];
    const float* slow = (const float*)d_in[1];
    const float* gw   = (const float*)d_in[2];
    const float* gb   = (const float*)d_in[3];
    const float* thw  = (const float*)d_in[4];
    const float* thb  = (const float*)d_in[5];
    const float* phw  = (const float*)d_in[6];
    const float* phb  = (const float*)d_in[7];
    const float* wzw  = (const float*)d_in[8];
    const float* wzb  = (const float*)d_in[9];
    const float* bng  = (const float*)d_in[10];
    const float* bnb  = (const float*)d_in[11];
    float* out = (float*)d_out;

    static int smem_set = 0;
    if (!smem_set) {
        cudaFuncSetAttribute(k_attn_tc, cudaFuncAttributeMaxDynamicSharedMemorySize,
                             SM_TOT * 4);
        smem_set = 1;
    }

    k_prep   <<<448, 256>>>(fast, slow, gw, gb, thw, thb, phw, phb);
    k_nop    <<<1, 32>>>();     // keeps the ncu capture slot on k_attn_tc
    k_attn_tc<<<128, 512, SM_TOT * 4>>>(wzw, wzb);
    k_final  <<<640, 512>>>(bng, bnb, out);
}

// round 16
// speedup vs baseline: 1.0083x; 1.0083x over previous
#include <cuda_runtime.h>
#include <cuda_bf16.h>
#include <math.h>
#include <stdint.h>

#define N_TOK 4096
#define CIN 80
#define CMID 40

// ---------------- scratch (device globals; no allocs allowed) ----------------
__device__ float    g_xs[CIN * N_TOK];       // downsampled slow
__device__ uint32_t g_qhi[N_TOK * 44];       // theta tf32, padded [n][44]
__device__ uint32_t g_khi[N_TOK * 48];       // phi tf32, fragment-permuted rows
__device__ uint32_t g_vp[64 * 1664];         // V bf16 pairs, fragment-permuted per tile
__device__ float    g_wy[CIN * N_TOK];       // [c][n]
__device__ float    g_sum[CIN];
__device__ float    g_sumsq[CIN];

// ---------------- helpers ------------------------------------------------------
__device__ __forceinline__ uint32_t f2tf(float x) {
    uint32_t r; asm("cvt.rna.tf32.f32 %0, %1;" : "=r"(r) : "f"(x)); return r;
}
__device__ __forceinline__ uint32_t packbf(float lo, float hi) {
    uint32_t r; asm("cvt.rn.bf16x2.f32 %0, %1, %2;" : "=r"(r) : "f"(hi), "f"(lo)); return r;
}

__device__ __forceinline__ void mma8(float c[4], uint32_t a0, uint32_t a1, uint32_t a2, uint32_t a3,
                                     uint32_t b0, uint32_t b1) {
    asm volatile("mma.sync.aligned.m16n8k8.row.col.f32.tf32.tf32.f32 "
                 "{%0,%1,%2,%3}, {%4,%5,%6,%7}, {%8,%9}, {%0,%1,%2,%3};"
                 : "+f"(c[0]), "+f"(c[1]), "+f"(c[2]), "+f"(c[3])
                 : "r"(a0), "r"(a1), "r"(a2), "r"(a3), "r"(b0), "r"(b1));
}
__device__ __forceinline__ void mma16(float c[4], uint32_t a0, uint32_t a1, uint32_t a2, uint32_t a3,
                                      uint32_t b0, uint32_t b1) {
    asm volatile("mma.sync.aligned.m16n8k16.row.col.f32.bf16.bf16.f32 "
                 "{%0,%1,%2,%3}, {%4,%5,%6,%7}, {%8,%9}, {%0,%1,%2,%3};"
                 : "+f"(c[0]), "+f"(c[1]), "+f"(c[2]), "+f"(c[3])
                 : "r"(a0), "r"(a1), "r"(a2), "r"(a3), "r"(b0), "r"(b1));
}

__device__ __forceinline__ void cpa16(uint32_t dst, const void* src) {
    asm volatile("cp.async.cg.shared.global [%0], [%1], 16;" :: "r"(dst), "l"(src));
}
__device__ __forceinline__ void cpa_commit() { asm volatile("cp.async.commit_group;"); }
__device__ __forceinline__ void cpa_wait0()  { asm volatile("cp.async.wait_group 0;"); }

__device__ __forceinline__ uint32_t smem_u32(const void* p) {
    uint32_t r;
    asm("{ .reg .u64 t; cvta.to.shared.u64 t, %1; cvt.u32.u64 %0, t; }" : "=r"(r) : "l"(p));
    return r;
}

__device__ __forceinline__ void wg_bar(int wg) {
    asm volatile("bar.sync %0, 256;" :: "r"(wg + 1) : "memory");
}

// ---------------- downsample weights (jax linear, antialias=True) -------------
__device__ __forceinline__ void down_w(int o, int& r0, float w[4]) {
    if (o == 0)        { r0 = -1; w[0] = 0.f;       w[1] = 3.f/7.f; w[2] = 3.f/7.f; w[3] = 1.f/7.f; }
    else if (o == 31)  { r0 = 61; w[0] = 1.f/7.f;   w[1] = 3.f/7.f; w[2] = 3.f/7.f; w[3] = 0.f; }
    else               { r0 = 2*o - 1; w[0] = 0.125f; w[1] = 0.375f; w[2] = 0.375f; w[3] = 0.125f; }
}

// ---------------- 1) FUSED prep: [0..127] proj(fast) | [128..447] down(slow) --
__global__ void __launch_bounds__(256) k_prep(const float* __restrict__ fast,
                       const float* __restrict__ slow,
                       const float* __restrict__ gw, const float* __restrict__ gb,
                       const float* __restrict__ thw, const float* __restrict__ thb,
                       const float* __restrict__ phw, const float* __restrict__ phb) {
    __shared__ float smbuf[12288];   // 48KB union
    int p = blockIdx.x;
    int tid = threadIdx.x;

    if (p >= 128) {
        // ---- slow-path downsample: plane q = p-128 (c*4+t) ----
        int q = p - 128;
        if (q == 0) {
            if (tid < 80)       g_sum[tid] = 0.f;
            else if (tid < 160) g_sumsq[tid - 80] = 0.f;
        }
        float* s = smbuf;
        const float* plane = slow + (size_t)q * 4096;
        for (int i = tid; i < 4096; i += 256) s[i] = plane[i];
        __syncthreads();
        for (int i = tid; i < 1024; i += 256) {
            int ho = i >> 5, wo = i & 31;
            int rh, rw; float wh[4], ww[4];
            down_w(ho, rh, wh);
            down_w(wo, rw, ww);
            float acc = 0.f;
#pragma unroll
            for (int a = 0; a < 4; a++) {
                int r = min(max(rh + a, 0), 63);
                float rowacc = 0.f;
#pragma unroll
                for (int b = 0; b < 4; b++) {
                    int cc = min(max(rw + b, 0), 63);
                    rowacc += ww[b] * s[r * 64 + cc];
                }
                acc += wh[a] * rowacc;
            }
            g_xs[q * 1024 + i] = acc;
        }
        return;
    }

    // ---- fast-path: downsample + projection for (t,h) slab of 32 tokens ----
    float* Ws = smbuf;               // 9600
    float* Bs = smbuf + 9600;        // 120 (pad to 128)
    float* Xs = smbuf + 9728;        // 2560
    int t = p >> 5, h = p & 31;

    for (int i = tid; i < 3200; i += 256) {
        Ws[i]        = thw[i];
        Ws[3200 + i] = phw[i];
        Ws[6400 + i] = gw[i];
    }
    if (tid < 120) {
        int o = tid;
        Bs[o] = (o < 40) ? thb[o] : (o < 80 ? phb[o - 40] : gb[o - 80]);
    }

    int rh; float wh[4];
    down_w(h, rh, wh);
    int rr[4];
#pragma unroll
    for (int a = 0; a < 4; a++) rr[a] = min(max(rh + a, 0), 63);
#pragma unroll
    for (int k = 0; k < 10; k++) {
        int i = tid + 256 * k;
        int c = i >> 5, wo = i & 31;
        int rw; float ww[4];
        down_w(wo, rw, ww);
        int cc[4];
#pragma unroll
        for (int b = 0; b < 4; b++) cc[b] = min(max(rw + b, 0), 63);
        const float* base = fast + ((size_t)(c * 4 + t)) * 4096;
        float acc = 0.f;
#pragma unroll
        for (int a = 0; a < 4; a++) {
            const float* row = base + rr[a] * 64;
            float rowacc = ww[0] * __ldg(row + cc[0]) + ww[1] * __ldg(row + cc[1])
                         + ww[2] * __ldg(row + cc[2]) + ww[3] * __ldg(row + cc[3]);
            acc += wh[a] * rowacc;
        }
        Xs[c * 32 + wo] = acc;
    }
    __syncthreads();

    int n  = tid & 31;
    int og = tid >> 5;
    float acc[15];
#pragma unroll
    for (int j = 0; j < 15; j++) acc[j] = Bs[og + 8 * j];
    for (int c = 0; c < 80; c++) {
        float xv = Xs[c * 32 + n];
#pragma unroll
        for (int j = 0; j < 15; j++) acc[j] += Ws[(og + 8 * j) * 80 + c] * xv;
    }
    int nn = p * 32 + n;
    int tile = nn >> 6, key = nn & 63;
#pragma unroll
    for (int j = 0; j < 15; j++) {
        int o = og + 8 * j;
        float v = acc[j];
        if (o < 40) {
            g_qhi[nn * 44 + o] = f2tf(v);
        } else if (o < 80) {
            int k = o - 40;
            g_khi[nn * 48 + (k & 3) * 12 + (k >> 2)] = f2tf(v);
        } else {
            int d = o - 80;
            int pair = key >> 1, b = key & 1;
            int wc = pair >> 3, m = pair & 7;
            int tg = m & 3, mp = m >> 2;
            int off = wc * 416 + tg * 104 + (d & 7) * 12 + (d >> 3) * 2 + mp;
            ((__nv_bfloat16*)g_vp)[((size_t)tile * 1664 + off) * 2 + b] = __float2bfloat16(v);
        }
    }
}

// ---------------- 2) attention + wz projection + BN stats (fused) -----------
#define SM_QH   0
#define WG_BASE 1408
#define WG_STRIDE 18944
#define WG_VOFF 12288
#define SM_SML  39296
#define SM_O1   39552
#define SM_L1   40832
#define SM_YS   40864
#define SM_WZS  42144
#define SM_TOT  45344

__device__ __forceinline__ void stage_kv(uint32_t sb, int tile, int wg, int buf, int wtid) {
    const char* sk = (const char*)(g_khi + tile * 3072);
    uint32_t dk = sb + (WG_BASE + wg * WG_STRIDE + buf * 3072) * 4;
#pragma unroll
    for (int i = wtid * 16; i < 768 * 16; i += 256 * 16)
        cpa16(dk + i, sk + i);
    const char* sv = (const char*)(g_vp + (size_t)tile * 1664);
    uint32_t dv = sb + (WG_BASE + wg * WG_STRIDE + WG_VOFF + buf * 1664) * 4;
#pragma unroll
    for (int i = wtid * 16; i < 416 * 16; i += 256 * 16)
        cpa16(dv + i, sv + i);
}

__global__ void __launch_bounds__(512, 1) k_attn_tc(const float* __restrict__ wzw,
                                                    const float* __restrict__ wzb) {
    extern __shared__ uint32_t sm[];
    uint32_t sb = smem_u32(sm);

    int tid  = threadIdx.x;
    int lane = tid & 31, wid = tid >> 5;
    int g = lane >> 2, tig = lane & 3;
    int wg = tid >> 8;
    int wtid = tid & 255;
    int wlocal = wid & 7;
    int warp_m = wlocal & 1, warp_c = wlocal >> 1;
    int m0 = blockIdx.x * 32;
    int rb = warp_m * 16;
    int r0 = rb + g, r1 = rb + g + 8;
    int wgt0 = wg * 32;

    {
        const char* sqh = (const char*)(g_qhi + m0 * 44);
#pragma unroll
        for (int i = tid * 16; i < 352 * 16; i += 512 * 16)
            cpa16(sb + i, sqh + i);
        stage_kv(sb, wgt0,     wg, 0, wtid);
        stage_kv(sb, wgt0 + 1, wg, 1, wtid);
        cpa_commit();
        cpa_wait0();
        __syncthreads();
    }

    uint32_t qh[5][4];
#pragma unroll
    for (int ks = 0; ks < 5; ks++) {
        int k0 = 8 * ks;
        qh[ks][0] = sm[SM_QH + r0 * 44 + k0 + tig];
        qh[ks][1] = sm[SM_QH + r1 * 44 + k0 + tig];
        qh[ks][2] = sm[SM_QH + r0 * 44 + k0 + tig + 4];
        qh[ks][3] = sm[SM_QH + r1 * 44 + k0 + tig + 4];
    }

    float oacc[5][4];
#pragma unroll
    for (int i = 0; i < 5; i++)
#pragma unroll
        for (int j = 0; j < 4; j++) oacc[i][j] = 0.f;
    float l0 = 0.f, l1 = 0.f;

    const uint32_t* wgk = sm + WG_BASE + wg * WG_STRIDE;
    const uint32_t* wgv = wgk + WG_VOFF;

    auto do_tile = [&](int buf) {
        const uint32_t* kh = wgk + buf * 3072;
        const uint32_t* vt = wgv + buf * 1664;

        uint32_t kv[2][10];
#pragma unroll
        for (int nt = 0; nt < 2; nt++) {
            const uint32_t* kp = kh + (16 * warp_c + 8 * nt + g) * 48 + tig * 12;
            uint4 a = *(const uint4*)kp;
            uint4 b = *(const uint4*)(kp + 4);
            uint2 c = *(const uint2*)(kp + 8);
            kv[nt][0] = a.x; kv[nt][1] = a.y; kv[nt][2] = a.z; kv[nt][3] = a.w;
            kv[nt][4] = b.x; kv[nt][5] = b.y; kv[nt][6] = b.z; kv[nt][7] = b.w;
            kv[nt][8] = c.x; kv[nt][9] = c.y;
        }

        float sA[2][4], sB[2][4];
#pragma unroll
        for (int i = 0; i < 2; i++)
#pragma unroll
            for (int j = 0; j < 4; j++) { sA[i][j] = 0.f; sB[i][j] = 0.f; }
#pragma unroll
        for (int nt = 0; nt < 2; nt++) {
            mma8(sA[nt], qh[0][0], qh[0][1], qh[0][2], qh[0][3], kv[nt][0], kv[nt][1]);
            mma8(sB[nt], qh[1][0], qh[1][1], qh[1][2], qh[1][3], kv[nt][2], kv[nt][3]);
            mma8(sA[nt], qh[2][0], qh[2][1], qh[2][2], qh[2][3], kv[nt][4], kv[nt][5]);
            mma8(sB[nt], qh[3][0], qh[3][1], qh[3][2], qh[3][3], kv[nt][6], kv[nt][7]);
            mma8(sA[nt], qh[4][0], qh[4][1], qh[4][2], qh[4][3], kv[nt][8], kv[nt][9]);
        }

        uint32_t vv[10];
        {
            const uint32_t* vpp = vt + warp_c * 416 + tig * 104 + g * 12;
            uint4 a = *(const uint4*)vpp;
            uint4 b = *(const uint4*)(vpp + 4);
            uint2 c = *(const uint2*)(vpp + 8);
            vv[0] = a.x; vv[1] = a.y; vv[2] = a.z; vv[3] = a.w;
            vv[4] = b.x; vv[5] = b.y; vv[6] = b.z; vv[7] = b.w;
            vv[8] = c.x; vv[9] = c.y;
        }

        float p[2][4];
#pragma unroll
        for (int nt = 0; nt < 2; nt++) {
#pragma unroll
            for (int j = 0; j < 4; j++) p[nt][j] = __expf(sA[nt][j] + sB[nt][j]);
            l0 += p[nt][0] + p[nt][1];
            l1 += p[nt][2] + p[nt][3];
        }

        uint32_t pa[4], pl[4];
#pragma unroll
        for (int nt = 0; nt < 2; nt++) {
            uint32_t h0 = packbf(p[nt][0], p[nt][1]);
            uint32_t h1 = packbf(p[nt][2], p[nt][3]);
            pa[2 * nt]     = h0;
            pa[2 * nt + 1] = h1;
            pl[2 * nt]     = packbf(p[nt][0] - __uint_as_float(h0 << 16),
                                    p[nt][1] - __uint_as_float(h0 & 0xffff0000u));
            pl[2 * nt + 1] = packbf(p[nt][2] - __uint_as_float(h1 << 16),
                                    p[nt][3] - __uint_as_float(h1 & 0xffff0000u));
        }

#pragma unroll
        for (int j = 0; j < 5; j++) {
            mma16(oacc[j], pa[0], pa[1], pa[2], pa[3], vv[2 * j], vv[2 * j + 1]);
            mma16(oacc[j], pl[0], pl[1], pl[2], pl[3], vv[2 * j], vv[2 * j + 1]);
        }
    };

    for (int it = 0; it < 16; it++) {
        int bp = (it & 1) << 1;
        if (it < 15) {
            int nbp = bp ^ 2;
            stage_kv(sb, wgt0 + 2 * it + 2, wg, nbp,     wtid);
            stage_kv(sb, wgt0 + 2 * it + 3, wg, nbp + 1, wtid);
            cpa_commit();
        }
        do_tile(bp);
        do_tile(bp + 1);
        if (it < 15) cpa_wait0();
        wg_bar(wg);
    }

    // ---- epilogue ----
    l0 += __shfl_xor_sync(0xffffffffu, l0, 1);
    l0 += __shfl_xor_sync(0xffffffffu, l0, 2);
    l1 += __shfl_xor_sync(0xffffffffu, l1, 1);
    l1 += __shfl_xor_sync(0xffffffffu, l1, 2);

    float* SMLw = (float*)(sm + SM_SML) + wg * 128;
    float* Obw  = (float*)(sm + WG_BASE + wg * WG_STRIDE);
    float* O1   = (float*)(sm + SM_O1);
    float* L1   = (float*)(sm + SM_L1);
    float* ys   = (float*)(sm + SM_YS);
    float4* wzs = (float4*)(sm + SM_WZS);

    if (tig == 0) { SMLw[warp_c * 32 + r0] = l0; SMLw[warp_c * 32 + r1] = l1; }
    if (warp_c > 0) {
        int base = (warp_c - 1) * 1280 + warp_m * 640;
#pragma unroll
        for (int j = 0; j < 5; j++) {
            int d = 8 * j + 2 * tig;
            *(float2*)&Obw[base + g * 40 + d]       = make_float2(oacc[j][0], oacc[j][1]);
            *(float2*)&Obw[base + (g + 8) * 40 + d] = make_float2(oacc[j][2], oacc[j][3]);
        }
    }
    for (int i = tid; i < 800; i += 512) wzs[i] = ((const float4*)wzw)[i];
    __syncthreads();

    if (warp_c == 0) {
        float L0s = 0.f, L1s = 0.f;
#pragma unroll
        for (int wc = 0; wc < 4; wc++) {
            L0s += SMLw[wc * 32 + r0];
            L1s += SMLw[wc * 32 + r1];
        }
        float o0[5][4];
#pragma unroll
        for (int j = 0; j < 5; j++) {
            int d = 8 * j + 2 * tig;
            o0[j][0] = oacc[j][0]; o0[j][1] = oacc[j][1];
            o0[j][2] = oacc[j][2]; o0[j][3] = oacc[j][3];
#pragma unroll
            for (int w = 0; w < 3; w++) {
                int base = w * 1280 + warp_m * 640;
                o0[j][0] += Obw[base + g * 40 + d];
                o0[j][1] += Obw[base + g * 40 + d + 1];
                o0[j][2] += Obw[base + (g + 8) * 40 + d];
                o0[j][3] += Obw[base + (g + 8) * 40 + d + 1];
            }
        }
        if (wg == 1) {
#pragma unroll
            for (int j = 0; j < 5; j++) {
                int d = 8 * j + 2 * tig;
                *(float2*)&O1[r0 * 40 + d] = make_float2(o0[j][0], o0[j][1]);
                *(float2*)&O1[r1 * 40 + d] = make_float2(o0[j][2], o0[j][3]);
            }
            if (tig == 0) { L1[r0] = L0s; L1[r1] = L1s; }
            __syncthreads();
        } else {
            __syncthreads();
            float il0 = 1.f / (L0s + L1[r0]);
            float il1 = 1.f / (L1s + L1[r1]);
#pragma unroll
            for (int j = 0; j < 5; j++) {
                int d = 8 * j + 2 * tig;
                float2 a = *(float2*)&O1[r0 * 40 + d];
                float2 b = *(float2*)&O1[r1 * 40 + d];
                *(float2*)&ys[r0 * 40 + d] = make_float2((o0[j][0] + a.x) * il0, (o0[j][1] + a.y) * il0);
                *(float2*)&ys[r1 * 40 + d] = make_float2((o0[j][2] + b.x) * il1, (o0[j][3] + b.y) * il1);
            }
        }
    } else {
        __syncthreads();
    }
    __syncthreads();

    {
        int n = lane;
        float4 yr[10];
#pragma unroll
        for (int q = 0; q < 10; q++) yr[q] = *(float4*)&ys[n * 40 + 4 * q];
#pragma unroll
        for (int j = 0; j < 5; j++) {
            int c = wid * 5 + j;
            float acc = wzb[c];
#pragma unroll
            for (int q = 0; q < 10; q++) {
                float4 w = wzs[c * 10 + q];
                acc += w.x * yr[q].x + w.y * yr[q].y + w.z * yr[q].z + w.w * yr[q].w;
            }
            g_wy[c * N_TOK + m0 + n] = acc;
            float s = acc, s2 = acc * acc;
#pragma unroll
            for (int off = 16; off > 0; off >>= 1) {
                s  += __shfl_down_sync(0xffffffffu, s, off);
                s2 += __shfl_down_sync(0xffffffffu, s2, off);
            }
            if (lane == 0) {
                atomicAdd(&g_sum[c], s);
                atomicAdd(&g_sumsq[c], s2);
            }
        }
    }
}

// ---------------- 3) normalize * slow, upsample 32->64 (half-plane CTAs) -----
__device__ __forceinline__ void up_w(int h, int& j0, float& w1) {
    if (h == 0)        { j0 = 0;  w1 = 0.f; }
    else if (h == 63)  { j0 = 31; w1 = 0.f; }
    else {
        float s = 0.5f * (float)h - 0.25f;
        j0 = (int)s;
        w1 = s - (float)j0;
    }
}

__global__ void __launch_bounds__(512) k_final(const float* __restrict__ bng,
                                               const float* __restrict__ bnb,
                                               float* __restrict__ out) {
    __shared__ float z[1024];
    int p = blockIdx.x >> 1;       // plane (c*4+t)
    int half = blockIdx.x & 1;     // output-row half
    int c = p >> 2;
    float mean = g_sum[c] * (1.f / 4096.f);
    float var  = g_sumsq[c] * (1.f / 4096.f) - mean * mean;
    float rstd = rsqrtf(var + 1e-5f);
    float ga = bng[c], be = bnb[c];
    for (int i = threadIdx.x; i < 1024; i += 512) {
        float wv = g_wy[c * N_TOK + (p & 3) * 1024 + i];
        float xs = g_xs[p * 1024 + i];
        z[i] = ((wv - mean) * rstd * ga + be) * xs;
    }
    __syncthreads();
    int wo = threadIdx.x & 63;     // invariant (512 % 64 == 0)
    int jw; float wwv;
    up_w(wo, jw, wwv);
    int jw1 = min(jw + 1, 31);
    for (int i = threadIdx.x; i < 2048; i += 512) {
        int ho = (i >> 6) + half * 32;
        int jh; float wh;
        up_w(ho, jh, wh);
        int jh1 = min(jh + 1, 31);
        float v00 = z[jh * 32 + jw],  v01 = z[jh * 32 + jw1];
        float v10 = z[jh1 * 32 + jw], v11 = z[jh1 * 32 + jw1];
        float v = (1.f - wh) * ((1.f - wwv) * v00 + wwv * v01)
                +        wh  * ((1.f - wwv) * v10 + wwv * v11);
        out[(size_t)p * 4096 + ho * 64 + wo] = v;
    }
}

// ---------------- launch ------------------------------------------------------
extern "C" void kernel_launch(void* const* d_in, const int* in_sizes, int n_in,
                              void* d_out, int out_size) {
    (void)in_sizes; (void)n_in; (void)out_size;
    const float* fast = (const float*)d_in[0];
    const float* slow = (const float*)d_in[1];
    const float* gw   = (const float*)d_in[2];
    const float* gb   = (const float*)d_in[3];
    const float* thw  = (const float*)d_in[4];
    const float* thb  = (const float*)d_in[5];
    const float* phw  = (const float*)d_in[6];
    const float* phb  = (const float*)d_in[7];
    const float* wzw  = (const float*)d_in[8];
    const float* wzb  = (const float*)d_in[9];
    const float* bng  = (const float*)d_in[10];
    const float* bnb  = (const float*)d_in[11];
    float* out = (float*)d_out;

    static int smem_set = 0;
    if (!smem_set) {
        cudaFuncSetAttribute(k_attn_tc, cudaFuncAttributeMaxDynamicSharedMemorySize,
                             SM_TOT * 4);
        smem_set = 1;
    }

    k_prep   <<<448, 256>>>(fast, slow, gw, gb, thw, thb, phw, phb);
    k_attn_tc<<<128, 512, SM_TOT * 4>>>(wzw, wzb);
    k_final  <<<640, 512>>>(bng, bnb, out);
}

// round 17
// speedup vs baseline: 1.1855x; 1.1757x over previous
#include <cuda_runtime.h>
#include <cuda_bf16.h>
#include <math.h>
#include <stdint.h>

#define N_TOK 4096
#define CIN 80
#define CMID 40

// ---------------- scratch (device globals; no allocs allowed) ----------------
__device__ float    g_xs[CIN * N_TOK];       // downsampled slow
__device__ uint32_t g_qhi[N_TOK * 44];       // theta tf32, padded [n][44]
__device__ uint32_t g_khi[N_TOK * 48];       // phi tf32, fragment-permuted rows
__device__ uint32_t g_vp[64 * 1664];         // V bf16 pairs, fragment-permuted per tile
__device__ float    g_wy[CIN * N_TOK];       // [c][n]
__device__ float    g_sum[CIN];
__device__ float    g_sumsq[CIN];

// ---------------- helpers ------------------------------------------------------
__device__ __forceinline__ uint32_t f2tf(float x) {
    uint32_t r; asm("cvt.rna.tf32.f32 %0, %1;" : "=r"(r) : "f"(x)); return r;
}
__device__ __forceinline__ uint32_t packbf(float lo, float hi) {
    uint32_t r; asm("cvt.rn.bf16x2.f32 %0, %1, %2;" : "=r"(r) : "f"(hi), "f"(lo)); return r;
}

__device__ __forceinline__ void mma8(float c[4], uint32_t a0, uint32_t a1, uint32_t a2, uint32_t a3,
                                     uint32_t b0, uint32_t b1) {
    asm volatile("mma.sync.aligned.m16n8k8.row.col.f32.tf32.tf32.f32 "
                 "{%0,%1,%2,%3}, {%4,%5,%6,%7}, {%8,%9}, {%0,%1,%2,%3};"
                 : "+f"(c[0]), "+f"(c[1]), "+f"(c[2]), "+f"(c[3])
                 : "r"(a0), "r"(a1), "r"(a2), "r"(a3), "r"(b0), "r"(b1));
}
__device__ __forceinline__ void mma16(float c[4], uint32_t a0, uint32_t a1, uint32_t a2, uint32_t a3,
                                      uint32_t b0, uint32_t b1) {
    asm volatile("mma.sync.aligned.m16n8k16.row.col.f32.bf16.bf16.f32 "
                 "{%0,%1,%2,%3}, {%4,%5,%6,%7}, {%8,%9}, {%0,%1,%2,%3};"
                 : "+f"(c[0]), "+f"(c[1]), "+f"(c[2]), "+f"(c[3])
                 : "r"(a0), "r"(a1), "r"(a2), "r"(a3), "r"(b0), "r"(b1));
}

__device__ __forceinline__ void cpa16(uint32_t dst, const void* src) {
    asm volatile("cp.async.cg.shared.global [%0], [%1], 16;" :: "r"(dst), "l"(src));
}
__device__ __forceinline__ void cpa_commit() { asm volatile("cp.async.commit_group;"); }
__device__ __forceinline__ void cpa_wait0()  { asm volatile("cp.async.wait_group 0;"); }

__device__ __forceinline__ uint32_t smem_u32(const void* p) {
    uint32_t r;
    asm("{ .reg .u64 t; cvta.to.shared.u64 t, %1; cvt.u32.u64 %0, t; }" : "=r"(r) : "l"(p));
    return r;
}

__device__ __forceinline__ void wg_bar(int wg) {
    asm volatile("bar.sync %0, 256;" :: "r"(wg + 1) : "memory");
}

// ---------------- downsample weights (jax linear, antialias=True) -------------
__device__ __forceinline__ void down_w(int o, int& r0, float w[4]) {
    if (o == 0)        { r0 = -1; w[0] = 0.f;       w[1] = 3.f/7.f; w[2] = 3.f/7.f; w[3] = 1.f/7.f; }
    else if (o == 31)  { r0 = 61; w[0] = 1.f/7.f;   w[1] = 3.f/7.f; w[2] = 3.f/7.f; w[3] = 0.f; }
    else               { r0 = 2*o - 1; w[0] = 0.125f; w[1] = 0.375f; w[2] = 0.375f; w[3] = 0.125f; }
}

// ---------------- 1) FUSED prep, 512 thr: [0..127] proj(fast) | [128..287] down(slow x2)
__global__ void __launch_bounds__(512) k_prep(const float* __restrict__ fast,
                       const float* __restrict__ slow,
                       const float* __restrict__ gw, const float* __restrict__ gb,
                       const float* __restrict__ thw, const float* __restrict__ thb,
                       const float* __restrict__ phw, const float* __restrict__ phb) {
    __shared__ float smbuf[12288];   // 48KB union
    int p = blockIdx.x;
    int tid = threadIdx.x;

    if (p >= 128) {
        // ---- slow-path downsample: planes q = (p-128)*2 and +1 ----
        if (p == 128) {
            if (tid < 80)       g_sum[tid] = 0.f;
            else if (tid < 160) g_sumsq[tid - 80] = 0.f;
        }
        float* s = smbuf;
#pragma unroll
        for (int pl = 0; pl < 2; pl++) {
            int q = (p - 128) * 2 + pl;
            const float* plane = slow + (size_t)q * 4096;
            for (int i = tid; i < 4096; i += 512) s[i] = plane[i];
            __syncthreads();
            for (int i = tid; i < 1024; i += 512) {
                int ho = i >> 5, wo = i & 31;
                int rh, rw; float wh[4], ww[4];
                down_w(ho, rh, wh);
                down_w(wo, rw, ww);
                float acc = 0.f;
#pragma unroll
                for (int a = 0; a < 4; a++) {
                    int r = min(max(rh + a, 0), 63);
                    float rowacc = 0.f;
#pragma unroll
                    for (int b = 0; b < 4; b++) {
                        int cc = min(max(rw + b, 0), 63);
                        rowacc += ww[b] * s[r * 64 + cc];
                    }
                    acc += wh[a] * rowacc;
                }
                g_xs[q * 1024 + i] = acc;
            }
            __syncthreads();
        }
        return;
    }

    // ---- fast-path: downsample + projection for (t,h) slab of 32 tokens ----
    float* Ws = smbuf;               // 9600
    float* Bs = smbuf + 9600;        // 120 (pad to 128)
    float* Xs = smbuf + 9728;        // 2560
    int t = p >> 5, h = p & 31;

    for (int i = tid; i < 800; i += 512) {
        ((float4*)Ws)[i]        = ((const float4*)thw)[i];
        ((float4*)(Ws + 3200))[i] = ((const float4*)phw)[i];
        ((float4*)(Ws + 6400))[i] = ((const float4*)gw)[i];
    }
    if (tid < 120) {
        int o = tid;
        Bs[o] = (o < 40) ? thb[o] : (o < 80 ? phb[o - 40] : gb[o - 80]);
    }

    int rh; float wh[4];
    down_w(h, rh, wh);
    int rr[4];
#pragma unroll
    for (int a = 0; a < 4; a++) rr[a] = min(max(rh + a, 0), 63);
#pragma unroll
    for (int k = 0; k < 5; k++) {
        int i = tid + 512 * k;
        int c = i >> 5, wo = i & 31;
        int rw; float ww[4];
        down_w(wo, rw, ww);
        int cc[4];
#pragma unroll
        for (int b = 0; b < 4; b++) cc[b] = min(max(rw + b, 0), 63);
        const float* base = fast + ((size_t)(c * 4 + t)) * 4096;
        float acc = 0.f;
#pragma unroll
        for (int a = 0; a < 4; a++) {
            const float* row = base + rr[a] * 64;
            float rowacc = ww[0] * __ldg(row + cc[0]) + ww[1] * __ldg(row + cc[1])
                         + ww[2] * __ldg(row + cc[2]) + ww[3] * __ldg(row + cc[3]);
            acc += wh[a] * rowacc;
        }
        Xs[c * 32 + wo] = acc;
    }
    __syncthreads();

    // projection: 16 groups x 32 tokens, 8 channels/thread (o = grp + 16j, o<120)
    int n   = tid & 31;
    int grp = tid >> 5;              // 0..15
    float acc[8];
#pragma unroll
    for (int j = 0; j < 8; j++) {
        int o = grp + 16 * j;
        acc[j] = (o < 120) ? Bs[o] : 0.f;
    }
    for (int c = 0; c < 80; c++) {
        float xv = Xs[c * 32 + n];
#pragma unroll
        for (int j = 0; j < 8; j++) {
            int o = grp + 16 * j;
            if (o < 120) acc[j] += Ws[o * 80 + c] * xv;
        }
    }
    int nn = p * 32 + n;
    int tile = nn >> 6, key = nn & 63;
#pragma unroll
    for (int j = 0; j < 8; j++) {
        int o = grp + 16 * j;
        if (o >= 120) continue;
        float v = acc[j];
        if (o < 40) {
            g_qhi[nn * 44 + o] = f2tf(v);
        } else if (o < 80) {
            int k = o - 40;
            g_khi[nn * 48 + (k & 3) * 12 + (k >> 2)] = f2tf(v);
        } else {
            int d = o - 80;
            int pair = key >> 1, b = key & 1;
            int wc = pair >> 3, m = pair & 7;
            int tg = m & 3, mp = m >> 2;
            int off = wc * 416 + tg * 104 + (d & 7) * 12 + (d >> 3) * 2 + mp;
            ((__nv_bfloat16*)g_vp)[((size_t)tile * 1664 + off) * 2 + b] = __float2bfloat16(v);
        }
    }
}

// ---------------- 2) attention + wz projection + BN stats (fused) -----------
#define SM_QH   0
#define WG_BASE 1408
#define WG_STRIDE 18944
#define WG_VOFF 12288
#define SM_SML  39296
#define SM_O1   39552
#define SM_L1   40832
#define SM_YS   40864
#define SM_WZS  42144
#define SM_TOT  45344

__device__ __forceinline__ void stage_kv(uint32_t sb, int tile, int wg, int buf, int wtid) {
    const char* sk = (const char*)(g_khi + tile * 3072);
    uint32_t dk = sb + (WG_BASE + wg * WG_STRIDE + buf * 3072) * 4;
#pragma unroll
    for (int i = wtid * 16; i < 768 * 16; i += 256 * 16)
        cpa16(dk + i, sk + i);
    const char* sv = (const char*)(g_vp + (size_t)tile * 1664);
    uint32_t dv = sb + (WG_BASE + wg * WG_STRIDE + WG_VOFF + buf * 1664) * 4;
#pragma unroll
    for (int i = wtid * 16; i < 416 * 16; i += 256 * 16)
        cpa16(dv + i, sv + i);
}

__global__ void __launch_bounds__(512, 1) k_attn_tc(const float* __restrict__ wzw,
                                                    const float* __restrict__ wzb) {
    extern __shared__ uint32_t sm[];
    uint32_t sb = smem_u32(sm);

    int tid  = threadIdx.x;
    int lane = tid & 31, wid = tid >> 5;
    int g = lane >> 2, tig = lane & 3;
    int wg = tid >> 8;
    int wtid = tid & 255;
    int wlocal = wid & 7;
    int warp_m = wlocal & 1, warp_c = wlocal >> 1;
    int m0 = blockIdx.x * 32;
    int rb = warp_m * 16;
    int r0 = rb + g, r1 = rb + g + 8;
    int wgt0 = wg * 32;

    {
        const char* sqh = (const char*)(g_qhi + m0 * 44);
#pragma unroll
        for (int i = tid * 16; i < 352 * 16; i += 512 * 16)
            cpa16(sb + i, sqh + i);
        stage_kv(sb, wgt0,     wg, 0, wtid);
        stage_kv(sb, wgt0 + 1, wg, 1, wtid);
        cpa_commit();
        cpa_wait0();
        __syncthreads();
    }

    uint32_t qh[5][4];
#pragma unroll
    for (int ks = 0; ks < 5; ks++) {
        int k0 = 8 * ks;
        qh[ks][0] = sm[SM_QH + r0 * 44 + k0 + tig];
        qh[ks][1] = sm[SM_QH + r1 * 44 + k0 + tig];
        qh[ks][2] = sm[SM_QH + r0 * 44 + k0 + tig + 4];
        qh[ks][3] = sm[SM_QH + r1 * 44 + k0 + tig + 4];
    }

    float oacc[5][4];
#pragma unroll
    for (int i = 0; i < 5; i++)
#pragma unroll
        for (int j = 0; j < 4; j++) oacc[i][j] = 0.f;
    float l0 = 0.f, l1 = 0.f;

    const uint32_t* wgk = sm + WG_BASE + wg * WG_STRIDE;
    const uint32_t* wgv = wgk + WG_VOFF;

    auto do_tile = [&](int buf) {
        const uint32_t* kh = wgk + buf * 3072;
        const uint32_t* vt = wgv + buf * 1664;

        uint32_t kv[2][10];
#pragma unroll
        for (int nt = 0; nt < 2; nt++) {
            const uint32_t* kp = kh + (16 * warp_c + 8 * nt + g) * 48 + tig * 12;
            uint4 a = *(const uint4*)kp;
            uint4 b = *(const uint4*)(kp + 4);
            uint2 c = *(const uint2*)(kp + 8);
            kv[nt][0] = a.x; kv[nt][1] = a.y; kv[nt][2] = a.z; kv[nt][3] = a.w;
            kv[nt][4] = b.x; kv[nt][5] = b.y; kv[nt][6] = b.z; kv[nt][7] = b.w;
            kv[nt][8] = c.x; kv[nt][9] = c.y;
        }

        float sA[2][4], sB[2][4];
#pragma unroll
        for (int i = 0; i < 2; i++)
#pragma unroll
            for (int j = 0; j < 4; j++) { sA[i][j] = 0.f; sB[i][j] = 0.f; }
#pragma unroll
        for (int nt = 0; nt < 2; nt++) {
            mma8(sA[nt], qh[0][0], qh[0][1], qh[0][2], qh[0][3], kv[nt][0], kv[nt][1]);
            mma8(sB[nt], qh[1][0], qh[1][1], qh[1][2], qh[1][3], kv[nt][2], kv[nt][3]);
            mma8(sA[nt], qh[2][0], qh[2][1], qh[2][2], qh[2][3], kv[nt][4], kv[nt][5]);
            mma8(sB[nt], qh[3][0], qh[3][1], qh[3][2], qh[3][3], kv[nt][6], kv[nt][7]);
            mma8(sA[nt], qh[4][0], qh[4][1], qh[4][2], qh[4][3], kv[nt][8], kv[nt][9]);
        }

        uint32_t vv[10];
        {
            const uint32_t* vpp = vt + warp_c * 416 + tig * 104 + g * 12;
            uint4 a = *(const uint4*)vpp;
            uint4 b = *(const uint4*)(vpp + 4);
            uint2 c = *(const uint2*)(vpp + 8);
            vv[0] = a.x; vv[1] = a.y; vv[2] = a.z; vv[3] = a.w;
            vv[4] = b.x; vv[5] = b.y; vv[6] = b.z; vv[7] = b.w;
            vv[8] = c.x; vv[9] = c.y;
        }

        float p[2][4];
#pragma unroll
        for (int nt = 0; nt < 2; nt++) {
#pragma unroll
            for (int j = 0; j < 4; j++) p[nt][j] = __expf(sA[nt][j] + sB[nt][j]);
            l0 += p[nt][0] + p[nt][1];
            l1 += p[nt][2] + p[nt][3];
        }

        uint32_t pa[4], pl[4];
#pragma unroll
        for (int nt = 0; nt < 2; nt++) {
            uint32_t h0 = packbf(p[nt][0], p[nt][1]);
            uint32_t h1 = packbf(p[nt][2], p[nt][3]);
            pa[2 * nt]     = h0;
            pa[2 * nt + 1] = h1;
            pl[2 * nt]     = packbf(p[nt][0] - __uint_as_float(h0 << 16),
                                    p[nt][1] - __uint_as_float(h0 & 0xffff0000u));
            pl[2 * nt + 1] = packbf(p[nt][2] - __uint_as_float(h1 << 16),
                                    p[nt][3] - __uint_as_float(h1 & 0xffff0000u));
        }

#pragma unroll
        for (int j = 0; j < 5; j++) {
            mma16(oacc[j], pa[0], pa[1], pa[2], pa[3], vv[2 * j], vv[2 * j + 1]);
            mma16(oacc[j], pl[0], pl[1], pl[2], pl[3], vv[2 * j], vv[2 * j + 1]);
        }
    };

    for (int it = 0; it < 16; it++) {
        int bp = (it & 1) << 1;
        if (it < 15) {
            int nbp = bp ^ 2;
            stage_kv(sb, wgt0 + 2 * it + 2, wg, nbp,     wtid);
            stage_kv(sb, wgt0 + 2 * it + 3, wg, nbp + 1, wtid);
            cpa_commit();
        }
        do_tile(bp);
        do_tile(bp + 1);
        if (it < 15) cpa_wait0();
        wg_bar(wg);
    }

    // ---- epilogue ----
    l0 += __shfl_xor_sync(0xffffffffu, l0, 1);
    l0 += __shfl_xor_sync(0xffffffffu, l0, 2);
    l1 += __shfl_xor_sync(0xffffffffu, l1, 1);
    l1 += __shfl_xor_sync(0xffffffffu, l1, 2);

    float* SMLw = (float*)(sm + SM_SML) + wg * 128;
    float* Obw  = (float*)(sm + WG_BASE + wg * WG_STRIDE);
    float* O1   = (float*)(sm + SM_O1);
    float* L1   = (float*)(sm + SM_L1);
    float* ys   = (float*)(sm + SM_YS);
    float4* wzs = (float4*)(sm + SM_WZS);

    if (tig == 0) { SMLw[warp_c * 32 + r0] = l0; SMLw[warp_c * 32 + r1] = l1; }
    if (warp_c > 0) {
        int base = (warp_c - 1) * 1280 + warp_m * 640;
#pragma unroll
        for (int j = 0; j < 5; j++) {
            int d = 8 * j + 2 * tig;
            *(float2*)&Obw[base + g * 40 + d]       = make_float2(oacc[j][0], oacc[j][1]);
            *(float2*)&Obw[base + (g + 8) * 40 + d] = make_float2(oacc[j][2], oacc[j][3]);
        }
    }
    for (int i = tid; i < 800; i += 512) wzs[i] = ((const float4*)wzw)[i];
    __syncthreads();

    if (warp_c == 0) {
        float L0s = 0.f, L1s = 0.f;
#pragma unroll
        for (int wc = 0; wc < 4; wc++) {
            L0s += SMLw[wc * 32 + r0];
            L1s += SMLw[wc * 32 + r1];
        }
        float o0[5][4];
#pragma unroll
        for (int j = 0; j < 5; j++) {
            int d = 8 * j + 2 * tig;
            o0[j][0] = oacc[j][0]; o0[j][1] = oacc[j][1];
            o0[j][2] = oacc[j][2]; o0[j][3] = oacc[j][3];
#pragma unroll
            for (int w = 0; w < 3; w++) {
                int base = w * 1280 + warp_m * 640;
                o0[j][0] += Obw[base + g * 40 + d];
                o0[j][1] += Obw[base + g * 40 + d + 1];
                o0[j][2] += Obw[base + (g + 8) * 40 + d];
                o0[j][3] += Obw[base + (g + 8) * 40 + d + 1];
            }
        }
        if (wg == 1) {
#pragma unroll
            for (int j = 0; j < 5; j++) {
                int d = 8 * j + 2 * tig;
                *(float2*)&O1[r0 * 40 + d] = make_float2(o0[j][0], o0[j][1]);
                *(float2*)&O1[r1 * 40 + d] = make_float2(o0[j][2], o0[j][3]);
            }
            if (tig == 0) { L1[r0] = L0s; L1[r1] = L1s; }
            __syncthreads();
        } else {
            __syncthreads();
            float il0 = 1.f / (L0s + L1[r0]);
            float il1 = 1.f / (L1s + L1[r1]);
#pragma unroll
            for (int j = 0; j < 5; j++) {
                int d = 8 * j + 2 * tig;
                float2 a = *(float2*)&O1[r0 * 40 + d];
                float2 b = *(float2*)&O1[r1 * 40 + d];
                *(float2*)&ys[r0 * 40 + d] = make_float2((o0[j][0] + a.x) * il0, (o0[j][1] + a.y) * il0);
                *(float2*)&ys[r1 * 40 + d] = make_float2((o0[j][2] + b.x) * il1, (o0[j][3] + b.y) * il1);
            }
        }
    } else {
        __syncthreads();
    }
    __syncthreads();

    {
        int n = lane;
        float4 yr[10];
#pragma unroll
        for (int q = 0; q < 10; q++) yr[q] = *(float4*)&ys[n * 40 + 4 * q];
#pragma unroll
        for (int j = 0; j < 5; j++) {
            int c = wid * 5 + j;
            float acc = wzb[c];
#pragma unroll
            for (int q = 0; q < 10; q++) {
                float4 w = wzs[c * 10 + q];
                acc += w.x * yr[q].x + w.y * yr[q].y + w.z * yr[q].z + w.w * yr[q].w;
            }
            g_wy[c * N_TOK + m0 + n] = acc;
            float s = acc, s2 = acc * acc;
#pragma unroll
            for (int off = 16; off > 0; off >>= 1) {
                s  += __shfl_down_sync(0xffffffffu, s, off);
                s2 += __shfl_down_sync(0xffffffffu, s2, off);
            }
            if (lane == 0) {
                atomicAdd(&g_sum[c], s);
                atomicAdd(&g_sumsq[c], s2);
            }
        }
    }
}

// ---------------- 3) normalize * slow, upsample 32->64 (half-plane CTAs) -----
__device__ __forceinline__ void up_w(int h, int& j0, float& w1) {
    if (h == 0)        { j0 = 0;  w1 = 0.f; }
    else if (h == 63)  { j0 = 31; w1 = 0.f; }
    else {
        float s = 0.5f * (float)h - 0.25f;
        j0 = (int)s;
        w1 = s - (float)j0;
    }
}

__global__ void __launch_bounds__(512) k_final(const float* __restrict__ bng,
                                               const float* __restrict__ bnb,
                                               float* __restrict__ out) {
    __shared__ float z[1024];
    int p = blockIdx.x >> 1;
    int half = blockIdx.x & 1;
    int c = p >> 2;
    float mean = g_sum[c] * (1.f / 4096.f);
    float var  = g_sumsq[c] * (1.f / 4096.f) - mean * mean;
    float rstd = rsqrtf(var + 1e-5f);
    float ga = bng[c], be = bnb[c];
    for (int i = threadIdx.x; i < 1024; i += 512) {
        float wv = g_wy[c * N_TOK + (p & 3) * 1024 + i];
        float xs = g_xs[p * 1024 + i];
        z[i] = ((wv - mean) * rstd * ga + be) * xs;
    }
    __syncthreads();
    int wo = threadIdx.x & 63;
    int jw; float wwv;
    up_w(wo, jw, wwv);
    int jw1 = min(jw + 1, 31);
    for (int i = threadIdx.x; i < 2048; i += 512) {
        int ho = (i >> 6) + half * 32;
        int jh; float wh;
        up_w(ho, jh, wh);
        int jh1 = min(jh + 1, 31);
        float v00 = z[jh * 32 + jw],  v01 = z[jh * 32 + jw1];
        float v10 = z[jh1 * 32 + jw], v11 = z[jh1 * 32 + jw1];
        float v = (1.f - wh) * ((1.f - wwv) * v00 + wwv * v01)
                +        wh  * ((1.f - wwv) * v10 + wwv * v11);
        out[(size_t)p * 4096 + ho * 64 + wo] = v;
    }
}

// ---------------- launch ------------------------------------------------------
extern "C" void kernel_launch(void* const* d_in, const int* in_sizes, int n_in,
                              void* d_out, int out_size) {
    (void)in_sizes; (void)n_in; (void)out_size;
    const float* fast = (const float*)d_in[0];
    const float* slow = (const float*)d_in[1];
    const float* gw   = (const float*)d_in[2];
    const float* gb   = (const float*)d_in[3];
    const float* thw  = (const float*)d_in[4];
    const float* thb  = (const float*)d_in[5];
    const float* phw  = (const float*)d_in[6];
    const float* phb  = (const float*)d_in[7];
    const float* wzw  = (const float*)d_in[8];
    const float* wzb  = (const float*)d_in[9];
    const float* bng  = (const float*)d_in[10];
    const float* bnb  = (const float*)d_in[11];
    float* out = (float*)d_out;

    static int smem_set = 0;
    if (!smem_set) {
        cudaFuncSetAttribute(k_attn_tc, cudaFuncAttributeMaxDynamicSharedMemorySize,
                             SM_TOT * 4);
        smem_set = 1;
    }

    k_prep   <<<288, 512>>>(fast, slow, gw, gb, thw, thb, phw, phb);
    k_attn_tc<<<128, 512, SM_TOT * 4>>>(wzw, wzb);
    k_final  <<<640, 512>>>(bng, bnb, out);
}